// round 12
// baseline (speedup 1.0000x reference)
#include <cuda_runtime.h>
#include <cstdint>

#define BB 8
#define NN 1024
#define DD 64
#define HH 32

// Interleaved path assignment: 17 MUFU h's spread evenly among 32.
#define IS_MUFU(h) ((((h) + 1) * 17 >> 5) > ((h) * 17 >> 5))

#define ROWS_PB 32
#define N_PROJ_UNITS 512            // 2*B*N/ROWS_PB
#define N_TILES 2048                // B * 16 * 16

// Scratch (allocation-free rule -> device globals).
__device__ float g_ca[BB * NN * HH];
__device__ float g_dv[BB * NN * HH];
__device__ unsigned int g_proj_done;   // proj units completed (reset each run)
__device__ unsigned int g_obs;         // barrier-passed observers (reset each run)

using u64 = unsigned long long;

__device__ __forceinline__ u64 f2_add(u64 a, u64 b) {
    u64 r; asm("add.rn.f32x2 %0,%1,%2;" : "=l"(r) : "l"(a), "l"(b)); return r;
}
__device__ __forceinline__ u64 f2_mul(u64 a, u64 b) {
    u64 r; asm("mul.rn.f32x2 %0,%1,%2;" : "=l"(r) : "l"(a), "l"(b)); return r;
}
__device__ __forceinline__ u64 f2_fma(u64 a, u64 b, u64 c) {
    u64 r; asm("fma.rn.f32x2 %0,%1,%2,%3;" : "=l"(r) : "l"(a), "l"(b), "l"(c)); return r;
}
__device__ __forceinline__ u64 pack2(float lo, float hi) {
    u64 r; asm("mov.b64 %0,{%1,%2};" : "=l"(r) : "f"(lo), "f"(hi)); return r;
}
__device__ __forceinline__ void unpack2(u64 v, float& lo, float& hi) {
    asm("mov.b64 {%0,%1},%2;" : "=f"(lo), "=f"(hi) : "l"(v));
}
__device__ __forceinline__ float tanh_a(float x) {
    float r; asm("tanh.approx.f32 %0,%1;" : "=f"(r) : "f"(x)); return r;
}

#define ONE2 0x3F8000003F800000ULL

struct SmemP1 { float x[ROWS_PB][68]; float w[DD][HH]; };
struct SmemP2 { float u[64][36]; float v[HH][68]; u64 a2[HH]; };

// ---------------------------------------------------------------------------
// Fused single-launch kernel: natural tile grid (2048 CTAs, 1 tile each).
// bids < 512 additionally run one projection unit first; a flag barrier
// (monotonic counter, reset by last observer) gates tile staging.
// ---------------------------------------------------------------------------
__global__ __launch_bounds__(256, 5) void fused_kernel(
    const float* __restrict__ cell, const float* __restrict__ drug,
    const float* __restrict__ w_q, const float* __restrict__ w_k,
    const float* __restrict__ bias, const float* __restrict__ a_vec,
    float* __restrict__ out)
{
    __shared__ union { SmemP1 p1; SmemP2 p2; } sm;

    int tid = threadIdx.x;
    int bid = blockIdx.x;

    // ===================== Phase 1: projection (bids < 512) =====================
    if (bid < N_PROJ_UNITS) {
        const int blocks_per_side = (BB * NN) / ROWS_PB;   // 256
        bool is_drug = bid >= blocks_per_side;
        int row0 = (is_drug ? bid - blocks_per_side : bid) * ROWS_PB;
        const float* src = (is_drug ? drug : cell) + (size_t)row0 * DD;
        const float* W   = is_drug ? w_q : w_k;

#pragma unroll
        for (int k = 0; k < 2; k++) {
            int idx = tid + k * 256;         // float4 index 0..511
            int row = idx >> 4, d4 = idx & 15;
            float4 v = *reinterpret_cast<const float4*>(src + row * DD + d4 * 4);
            *reinterpret_cast<float4*>(&sm.p1.x[row][d4 * 4]) = v;
        }
#pragma unroll
        for (int k = 0; k < 2; k++) {
            int idx = tid + k * 256;
            *reinterpret_cast<float4*>(reinterpret_cast<float*>(sm.p1.w) + idx * 4) =
                *reinterpret_cast<const float4*>(W + idx * 4);
        }
        __syncthreads();

        int hq  = tid & 7;       // h = hq*4 + c
        int row = tid >> 3;      // 0..31

        float a0 = 0.f, a1 = 0.f, a2 = 0.f, a3 = 0.f;
#pragma unroll
        for (int d = 0; d < DD; d++) {
            float x = sm.p1.x[row][d];
            float4 w4 = *reinterpret_cast<float4*>(&sm.p1.w[d][hq * 4]);
            a0 = fmaf(x, w4.x, a0);
            a1 = fmaf(x, w4.y, a1);
            a2 = fmaf(x, w4.z, a2);
            a3 = fmaf(x, w4.w, a3);
        }

        int h0 = hq * 4;
        float o[4] = {a0, a1, a2, a3};
        if (is_drug) {
            float4 b4 = *reinterpret_cast<const float4*>(bias + h0);
            o[0] += b4.x; o[1] += b4.y; o[2] += b4.z; o[3] += b4.w;
        }
#pragma unroll
        for (int c = 0; c < 4; c++)
            if (!IS_MUFU(h0 + c)) o[c] = tanh_a(o[c]);   // Newton lanes tanh'd

        float* dst = (is_drug ? g_dv : g_ca) + (size_t)(row0 + row) * HH + h0;
        *reinterpret_cast<float4*>(dst) = make_float4(o[0], o[1], o[2], o[3]);

        __threadfence();          // make this thread's stores globally visible
        __syncthreads();          // all threads' fenced stores done; smem WAR
        if (tid == 0) atomicAdd(&g_proj_done, 1u);
    }

    // ===================== Flag barrier: wait for all 512 units =====================
    if (tid == 0) {
        while (*(volatile unsigned int*)&g_proj_done < (unsigned)N_PROJ_UNITS)
            __nanosleep(32);
        // Reset protocol: the 2048th CTA to PASS the barrier resets the
        // counters. At that point every CTA has passed (no one reads them
        // again this run), and graph replays are stream-sequential.
        unsigned int o = atomicAdd(&g_obs, 1u);
        if (o == (unsigned)(N_TILES - 1)) {
            g_proj_done = 0u;
            g_obs = 0u;
            __threadfence();
        }
    }
    __syncthreads();
    __threadfence();              // acquire: order g_ca/g_dv reads after flag

    // ===================== Phase 2: one co-attention tile =====================
    int jx = bid & 15;
    int iy = (bid >> 4) & 15;
    int b  = bid >> 8;
    int i0 = iy * 64, j0 = jx * 64;

    const float* ca = g_ca + (b * NN + i0) * HH;
    const float* dv = g_dv + (b * NN + j0) * HH;

#pragma unroll
    for (int k = 0; k < 2; k++) {
        int idx = tid + k * 256;       // 0..511
        int row = idx >> 3, g = idx & 7;
        float4 uu = *reinterpret_cast<const float4*>(ca + row * HH + 4 * g);
        *reinterpret_cast<float4*>(&sm.p2.u[row][4 * g]) = uu;
        float4 vv = *reinterpret_cast<const float4*>(dv + row * HH + 4 * g);
        sm.p2.v[4 * g + 0][row] = vv.x;
        sm.p2.v[4 * g + 1][row] = vv.y;
        sm.p2.v[4 * g + 2][row] = vv.z;
        sm.p2.v[4 * g + 3][row] = vv.w;
    }
    if (tid < HH) {
        float av = a_vec[tid];
        if (!IS_MUFU(tid)) av = -av;   // folds r = -s*z sign on Newton path
        sm.p2.a2[tid] = pack2(av, av);
    }
    __syncthreads();

    int tx = tid & 15;        // j quad (4 consecutive cols -> float4 store)
    int ty = tid >> 4;        // i quad

    u64 acc[4][2];
#pragma unroll
    for (int r = 0; r < 4; r++) { acc[r][0] = 0ULL; acc[r][1] = 0ULL; }

#pragma unroll
    for (int g = 0; g < 16; g++) {                // h-groups of 2 (mixed paths)
        float2 u2r[4];
#pragma unroll
        for (int r = 0; r < 4; r++)
            u2r[r] = *reinterpret_cast<float2*>(&sm.p2.u[ty * 4 + r][2 * g]);

#pragma unroll
        for (int k = 0; k < 2; k++) {
            const int h = 2 * g + k;              // compile-time
            float4 vv = *reinterpret_cast<float4*>(&sm.p2.v[h][tx * 4]);
            u64 v2[2] = { pack2(vv.x, vv.y), pack2(vv.z, vv.w) };
            u64 a2 = sm.p2.a2[h];

#pragma unroll
            for (int r = 0; r < 4; r++) {
                float us = k ? u2r[r].y : u2r[r].x;
                u64 up = pack2(us, us);
#pragma unroll
                for (int cp = 0; cp < 2; cp++) {
                    u64 s2 = f2_add(up, v2[cp]);
                    if (IS_MUFU(h)) {
                        float lo, hi; unpack2(s2, lo, hi);
                        u64 t2 = pack2(tanh_a(lo), tanh_a(hi));
                        acc[r][cp] = f2_fma(a2, t2, acc[r][cp]);
                    } else {
                        u64 d2 = f2_fma(up, v2[cp], ONE2);          // d = 1+tu*tv
                        float dl, dh; unpack2(d2, dl, dh);
                        u64 z = pack2(                               // z0 ~ -1/d seed
                            __uint_as_float(0xFEF311C3u - __float_as_uint(dl)),
                            __uint_as_float(0xFEF311C3u - __float_as_uint(dh)));
                        u64 e = f2_fma(d2, z, ONE2);                 // e = 1 + d*z
                        u64 p = f2_fma(e, e, e);                     // e + e^2
                        z     = f2_fma(z, p, z);                     // -1/d, err e^3
                        u64 pp = f2_mul(s2, z);                      // -s/d
                        acc[r][cp] = f2_fma(a2, pp, acc[r][cp]);     // a2 pre-negated
                    }
                }
            }
        }
    }

#pragma unroll
    for (int r = 0; r < 4; r++) {
        float o0, o1, o2, o3;
        unpack2(acc[r][0], o0, o1);
        unpack2(acc[r][1], o2, o3);
        int i = i0 + ty * 4 + r;
        *reinterpret_cast<float4*>(out + ((size_t)b * NN + i) * NN + j0 + tx * 4) =
            make_float4(o0, o1, o2, o3);
    }
}

extern "C" void kernel_launch(void* const* d_in, const int* in_sizes, int n_in,
                              void* d_out, int out_size)
{
    const float* cell = (const float*)d_in[0];
    const float* drug = (const float*)d_in[1];
    const float* w_q  = (const float*)d_in[2];
    const float* w_k  = (const float*)d_in[3];
    const float* bias = (const float*)d_in[4];
    const float* a    = (const float*)d_in[5];
    float* out = (float*)d_out;

    fused_kernel<<<N_TILES, 256>>>(cell, drug, w_q, w_k, bias, a, out);
}

// round 13
// speedup vs baseline: 1.0367x; 1.0367x over previous
#include <cuda_runtime.h>
#include <cstdint>

#define BB 8
#define NN 1024
#define DD 64
#define HH 32

// Interleaved path assignment: 17 MUFU h's spread evenly among 32.
#define IS_MUFU(h) ((((h) + 1) * 17 >> 5) > ((h) * 17 >> 5))

// Scratch (allocation-free rule -> device globals).
// MUFU h's: raw projection; Newton h's: tanh(projection).
__device__ float g_ca[BB * NN * HH];
__device__ float g_dv[BB * NN * HH];

using u64 = unsigned long long;

__device__ __forceinline__ u64 f2_add(u64 a, u64 b) {
    u64 r; asm("add.rn.f32x2 %0,%1,%2;" : "=l"(r) : "l"(a), "l"(b)); return r;
}
__device__ __forceinline__ u64 f2_mul(u64 a, u64 b) {
    u64 r; asm("mul.rn.f32x2 %0,%1,%2;" : "=l"(r) : "l"(a), "l"(b)); return r;
}
__device__ __forceinline__ u64 f2_fma(u64 a, u64 b, u64 c) {
    u64 r; asm("fma.rn.f32x2 %0,%1,%2,%3;" : "=l"(r) : "l"(a), "l"(b), "l"(c)); return r;
}
__device__ __forceinline__ u64 pack2(float lo, float hi) {
    u64 r; asm("mov.b64 %0,{%1,%2};" : "=l"(r) : "f"(lo), "f"(hi)); return r;
}
__device__ __forceinline__ void unpack2(u64 v, float& lo, float& hi) {
    asm("mov.b64 {%0,%1},%2;" : "=f"(lo), "=f"(hi) : "l"(v));
}
__device__ __forceinline__ float tanh_a(float x) {
    float r; asm("tanh.approx.f32 %0,%1;" : "=f"(r) : "f"(x)); return r;
}

#define ONE2 0x3F8000003F800000ULL

// ---------------------------------------------------------------------------
// Projection v2 (short critical path): 1024 blocks x 16 rows, 256 threads.
// Each thread: 1 row, 2 consecutive h. Staging = 3 LDG.128/thread, ONE round,
// one barrier. Compute = 64 x (LDS bcast + LDS.64 + 2 FFMA), conflict-free.
// MUFU-h outputs raw, Newton-h outputs tanh'd.
// ---------------------------------------------------------------------------
#define ROWS_PB 16
__global__ __launch_bounds__(256) void proj_kernel(
    const float* __restrict__ cell, const float* __restrict__ drug,
    const float* __restrict__ w_q, const float* __restrict__ w_k,
    const float* __restrict__ bias)
{
    __shared__ float s_x[ROWS_PB][68];   // padded rows
    __shared__ float s_w[DD][HH];        // 8 KB, same layout as global W

    int tid = threadIdx.x;
    int blk = blockIdx.x;                            // 0..1023
    const int blocks_per_side = (BB * NN) / ROWS_PB; // 512
    bool is_drug = blk >= blocks_per_side;
    int row0 = (is_drug ? blk - blocks_per_side : blk) * ROWS_PB;
    const float* src = (is_drug ? drug : cell) + (size_t)row0 * DD;
    const float* W   = is_drug ? w_q : w_k;

    // Stage x: 16 rows x 16 float4 = 256 float4, exactly 1 per thread.
    {
        int row = tid >> 4, d4 = tid & 15;
        float4 v = *reinterpret_cast<const float4*>(src + row * DD + d4 * 4);
        *reinterpret_cast<float4*>(&s_x[row][d4 * 4]) = v;
    }
    // Stage W: 512 float4, 2 per thread (independent, same round).
#pragma unroll
    for (int k = 0; k < 2; k++) {
        int idx = tid + k * 256;
        *reinterpret_cast<float4*>(reinterpret_cast<float*>(s_w) + idx * 4) =
            *reinterpret_cast<const float4*>(W + idx * 4);
    }
    __syncthreads();

    int hp  = tid & 15;      // h-pair: h = hp*2, hp*2+1
    int row = tid >> 4;      // 0..15

    float a0 = 0.f, a1 = 0.f;
#pragma unroll
    for (int d = 0; d < DD; d++) {
        float x = s_x[row][d];
        float2 w2 = *reinterpret_cast<float2*>(&s_w[d][hp * 2]);
        a0 = fmaf(x, w2.x, a0);
        a1 = fmaf(x, w2.y, a1);
    }

    int h0 = hp * 2;
    if (is_drug) {
        float2 b2 = *reinterpret_cast<const float2*>(bias + h0);
        a0 += b2.x; a1 += b2.y;
    }
    if (!IS_MUFU(h0))     a0 = tanh_a(a0);   // Newton lanes store tanh'd
    if (!IS_MUFU(h0 + 1)) a1 = tanh_a(a1);

    float* dst = (is_drug ? g_dv : g_ca) + (size_t)(row0 + row) * HH + h0;
    *reinterpret_cast<float2*>(dst) = make_float2(a0, a1);
}

// ---------------------------------------------------------------------------
// Co-attention (R6/R9 best variant + PDL): 64x64 tile/CTA, 4x4 outputs/thread,
// accumulators packed over j (4x2 f32x2).
// MUFU h:   e = u+v; tanh.approx on MUFU; acc += a*t
// Newton h: tanh(u+v) = (tu+tv)/(1+tu*tv); reciprocal = bit-seed + one fused
//           cubic correction z*(1+e+e^2) on the FMA pipe (err ~ e0^3).
// ---------------------------------------------------------------------------
__global__ __launch_bounds__(256, 5) void coattn_kernel(
    const float* __restrict__ a_vec, float* __restrict__ out)
{
    __shared__ float s_u[64][36];      // [i-row][h], padded (16B-aligned rows)
    __shared__ float s_v[HH][68];      // [h][j-col] transposed, padded
    __shared__ u64   s_a2[HH];         // (a_h, a_h), negated for Newton h

    int b  = blockIdx.z;
    int i0 = blockIdx.y * 64;
    int j0 = blockIdx.x * 64;
    int tid = threadIdx.x;

    // Independent preamble (inputs only, no proj dependency).
    if (tid < HH) {
        float av = a_vec[tid];
        if (!IS_MUFU(tid)) av = -av;   // folds r = -s*z sign on Newton path
        s_a2[tid] = pack2(av, av);
    }

    const float* ca = g_ca + (b * NN + i0) * HH;
    const float* dv = g_dv + (b * NN + j0) * HH;

    // Wait for proj_kernel's writes to g_ca/g_dv to be visible.
    cudaGridDependencySynchronize();

#pragma unroll
    for (int k = 0; k < 2; k++) {
        int idx = tid + k * 256;       // 0..511
        int row = idx >> 3, g = idx & 7;
        float4 uu = *reinterpret_cast<const float4*>(ca + row * HH + 4 * g);
        *reinterpret_cast<float4*>(&s_u[row][4 * g]) = uu;
        float4 vv = *reinterpret_cast<const float4*>(dv + row * HH + 4 * g);
        s_v[4 * g + 0][row] = vv.x;
        s_v[4 * g + 1][row] = vv.y;
        s_v[4 * g + 2][row] = vv.z;
        s_v[4 * g + 3][row] = vv.w;
    }
    __syncthreads();

    int tx = tid & 15;        // j quad (4 consecutive cols -> float4 store)
    int ty = tid >> 4;        // i quad

    u64 acc[4][2];
#pragma unroll
    for (int r = 0; r < 4; r++) { acc[r][0] = 0ULL; acc[r][1] = 0ULL; }

#pragma unroll
    for (int g = 0; g < 16; g++) {                // h-groups of 2 (mixed paths)
        float2 u2r[4];
#pragma unroll
        for (int r = 0; r < 4; r++)
            u2r[r] = *reinterpret_cast<float2*>(&s_u[ty * 4 + r][2 * g]);

#pragma unroll
        for (int k = 0; k < 2; k++) {
            const int h = 2 * g + k;              // compile-time
            float4 vv = *reinterpret_cast<float4*>(&s_v[h][tx * 4]);
            u64 v2[2] = { pack2(vv.x, vv.y), pack2(vv.z, vv.w) };
            u64 a2 = s_a2[h];

#pragma unroll
            for (int r = 0; r < 4; r++) {
                float us = k ? u2r[r].y : u2r[r].x;
                u64 up = pack2(us, us);
#pragma unroll
                for (int cp = 0; cp < 2; cp++) {
                    u64 s2 = f2_add(up, v2[cp]);
                    if (IS_MUFU(h)) {
                        float lo, hi; unpack2(s2, lo, hi);
                        u64 t2 = pack2(tanh_a(lo), tanh_a(hi));
                        acc[r][cp] = f2_fma(a2, t2, acc[r][cp]);
                    } else {
                        u64 d2 = f2_fma(up, v2[cp], ONE2);          // d = 1+tu*tv
                        float dl, dh; unpack2(d2, dl, dh);
                        u64 z = pack2(                               // z0 ~ -1/d seed
                            __uint_as_float(0xFEF311C3u - __float_as_uint(dl)),
                            __uint_as_float(0xFEF311C3u - __float_as_uint(dh)));
                        u64 e = f2_fma(d2, z, ONE2);                 // e = 1 + d*z
                        u64 p = f2_fma(e, e, e);                     // e + e^2
                        z     = f2_fma(z, p, z);                     // z(1+e+e^2): -1/d, err e^3
                        u64 pp = f2_mul(s2, z);                      // -s/d
                        acc[r][cp] = f2_fma(a2, pp, acc[r][cp]);     // a2 pre-negated
                    }
                }
            }
        }
    }

    // Stores come straight from the j-packed accumulators.
#pragma unroll
    for (int r = 0; r < 4; r++) {
        float o0, o1, o2, o3;
        unpack2(acc[r][0], o0, o1);
        unpack2(acc[r][1], o2, o3);
        int i = i0 + ty * 4 + r;
        *reinterpret_cast<float4*>(out + ((size_t)b * NN + i) * NN + j0 + tx * 4) =
            make_float4(o0, o1, o2, o3);
    }
}

extern "C" void kernel_launch(void* const* d_in, const int* in_sizes, int n_in,
                              void* d_out, int out_size)
{
    const float* cell = (const float*)d_in[0];
    const float* drug = (const float*)d_in[1];
    const float* w_q  = (const float*)d_in[2];
    const float* w_k  = (const float*)d_in[3];
    const float* bias = (const float*)d_in[4];
    const float* a    = (const float*)d_in[5];
    float* out = (float*)d_out;

    proj_kernel<<<2 * (BB * NN) / ROWS_PB, 256>>>(cell, drug, w_q, w_k, bias);

    // Co-attention with programmatic dependent launch: CTAs may pre-launch and
    // run their preamble; cudaGridDependencySynchronize() in-kernel gates the
    // g_ca/g_dv reads on proj completion.
    cudaLaunchConfig_t cfg = {};
    cfg.gridDim  = dim3(NN / 64, NN / 64, BB);
    cfg.blockDim = dim3(256, 1, 1);
    cfg.dynamicSmemBytes = 0;
    cfg.stream = 0;
    cudaLaunchAttribute attrs[1];
    attrs[0].id = cudaLaunchAttributeProgrammaticStreamSerialization;
    attrs[0].val.programmaticStreamSerializationAllowed = 1;
    cfg.attrs = attrs;
    cfg.numAttrs = 1;
    cudaLaunchKernelEx(&cfg, coattn_kernel, a, out);
}